// round 10
// baseline (speedup 1.0000x reference)
#include <cuda_runtime.h>
#include <cstdint>

// Fixed problem shapes
#define BATCH   4
#define N_PER   300
#define IN_DIM  256
#define KEY_DIM 32
#define HW      25600       // 160*160
#define NT2P    40          // stage2 n-tiles padded (300->320)
#define FSTR    132         // feat/key smem row stride (floats)

// seg_mma smem byte offsets (dynamic)
#define SM_FEAT0 0
#define SM_FEAT1 16896      // 32*132*4
#define SM_KEY   0          // key tile [32 o][FSTR] overlaps feat buf0
#define SM_TOTAL 33792      // two feat buffers only

// qproj smem: w [32][65 float4] + x [8][64 float4] + q [8][32] f32
#define QP_W     0
#define QP_X     33280
#define QP_Q     41472
#define QP_TOTAL 42496

typedef unsigned int u32;

__device__ uint4 g_kwf[16 * 4 * 32];            // [kt16][nt][lane] hi/lo frag
__device__ uint4 g_qf[BATCH * 2 * NT2P * 32];   // [b][kt16][nt][lane] (.bss zero)

// ---------------------------------------------------------------------------
__device__ __forceinline__ u32 packbf(float flo, float fhi) {
    u32 r; asm("cvt.rn.bf16x2.f32 %0, %1, %2;" : "=r"(r) : "f"(fhi), "f"(flo));
    return r;
}
__device__ __forceinline__ u32 split_pair(float f0, float f1, u32& lo) {
    u32 h = packbf(f0, f1);
    float h0 = __uint_as_float(h << 16);
    float h1 = __uint_as_float(h & 0xffff0000u);
    lo = packbf(f0 - h0, f1 - h1);
    return h;
}
__device__ __forceinline__ void mma_bf16(float d[4], const u32 a[4], u32 b0, u32 b1) {
    asm volatile(
        "mma.sync.aligned.m16n8k16.row.col.f32.bf16.bf16.f32 "
        "{%0,%1,%2,%3}, {%4,%5,%6,%7}, {%8,%9}, {%0,%1,%2,%3};"
        : "+f"(d[0]), "+f"(d[1]), "+f"(d[2]), "+f"(d[3])
        : "r"(a[0]), "r"(a[1]), "r"(a[2]), "r"(a[3]), "r"(b0), "r"(b1));
}
__device__ __forceinline__ void cp16(u32 saddr, const void* g) {
    asm volatile("cp.async.cg.shared.global [%0], [%1], 16;" :: "r"(saddr), "l"(g));
}
#define CP_COMMIT()  asm volatile("cp.async.commit_group;" ::: "memory")
#define CP_WAITALL() asm volatile("cp.async.wait_group 0;" ::: "memory")

// ---------------------------------------------------------------------------
// qproj + q fragment pack + kw fragment pack (first 8 blocks of b=0).
// PDL trigger AFTER kw pack + fence: seg's stage-1 g_kwf reads are ordered.
// grid (38, 4), 256 thr, block = 8 q-rows.
// ---------------------------------------------------------------------------
__global__ void qproj_kernel(const float* __restrict__ in_feats,
                             const float* __restrict__ qry_w,
                             const float* __restrict__ qry_b,
                             const float* __restrict__ key_w) {
    extern __shared__ char qsm[];
    const float4* w_s4 = (const float4*)(qsm + QP_W);   // stride 65 float4/row
    const float4* x_s4 = (const float4*)(qsm + QP_X);   // stride 64 float4/row
    float*        q_s  = (float*)(qsm + QP_Q);          // [8][32]
    const u32 sb = (u32)__cvta_generic_to_shared(qsm);

    const int tid = threadIdx.x;
    const int b   = blockIdx.y;
    const int nt  = blockIdx.x;                 // n-tile (8 rows)
    const int n0  = nt * 8;

    // stage qry_w (32 x 64 float4, padded rows) + x rows
#pragma unroll
    for (int k = 0; k < 8; k++) {
        int idx = k * 256 + tid;
        int o = idx >> 6, i = idx & 63;
        cp16(sb + QP_W + (u32)(o * 65 + i) * 16, qry_w + o * IN_DIM + i * 4);
    }
#pragma unroll
    for (int k = 0; k < 2; k++) {
        int idx = k * 256 + tid;
        int row = idx >> 6, i = idx & 63;
        int n = n0 + row; if (n >= N_PER) n = N_PER - 1;
        cp16(sb + QP_X + (u32)idx * 16,
             in_feats + ((size_t)b * N_PER + n) * IN_DIM + i * 4);
    }
    CP_COMMIT();

    // kw fragment pack, then fence, then trigger (all blocks trigger)
    if (b == 0 && nt < 8) {
        int idx = nt * 256 + tid;               // 0..2047
        int lane = idx & 31, nt1 = (idx >> 5) & 3, kt = idx >> 7;
        int t = lane & 3, g = lane >> 2;
        int o  = nt1 * 8 + g;
        int k0 = kt * 16 + 2 * t;
        float w00 = key_w[o * IN_DIM + k0],     w01 = key_w[o * IN_DIM + k0 + 1];
        float w10 = key_w[o * IN_DIM + k0 + 8], w11 = key_w[o * IN_DIM + k0 + 9];
        uint4 v;
        v.x = split_pair(w00, w01, v.z);
        v.y = split_pair(w10, w11, v.w);
        g_kwf[idx] = v;
        __threadfence();
    }
    cudaTriggerProgrammaticLaunchCompletion();

    CP_WAITALL();
    __syncthreads();

    const int w    = tid >> 5, lane = tid & 31;
    const int n    = n0 + w;

    float a0 = 0.f, a1 = 0.f, a2 = 0.f, a3 = 0.f;
#pragma unroll 8
    for (int i = 0; i < 64; i++) {
        float4 wv = w_s4[lane * 65 + i];        // conflict-free LDS.128
        float4 xv = x_s4[w * 64 + i];           // broadcast
        a0 = fmaf(xv.x, wv.x, a0);
        a1 = fmaf(xv.y, wv.y, a1);
        a2 = fmaf(xv.z, wv.z, a2);
        a3 = fmaf(xv.w, wv.w, a3);
    }
    float q = (n < N_PER) ? (a0 + a1) + (a2 + a3) + qry_b[lane] : 0.f;
    q_s[w * 32 + lane] = q;
    __syncthreads();

    if (tid < 64) {
        int kt = tid >> 5;
        int t = lane & 3, g = lane >> 2;
        const float* qr = q_s + g * 32 + kt * 16 + 2 * t;
        uint4 v;
        v.x = split_pair(qr[0], qr[1], v.z);
        v.y = split_pair(qr[8], qr[9], v.w);
        g_qf[((size_t)(b * 2 + kt) * NT2P + nt) * 32 + lane] = v;
    }
}

// ---------------------------------------------------------------------------
// Stage-2 chunk: JC n-tiles; key fragments hoisted (kh/kl); B frags batch-
// loaded from L2 (__ldg, MLP=2*JC) then consumed by MMAs.
// ---------------------------------------------------------------------------
template<int JC>
__device__ __forceinline__ void stage2_chunk(
    int nts, const uint4* __restrict__ qf_b, float* outb,
    const u32 kh[2][2][4], const u32 kl[2][2][4],
    int lane, int t, int colA)
{
    uint4 B[2][JC];
#pragma unroll
    for (int kt = 0; kt < 2; kt++)
#pragma unroll
        for (int j = 0; j < JC; j++)
            B[kt][j] = __ldg(qf_b + ((size_t)(kt * NT2P + nts + j)) * 32 + lane);

    float D2[2][JC][4];
#pragma unroll
    for (int m = 0; m < 2; m++)
#pragma unroll
        for (int j = 0; j < JC; j++)
#pragma unroll
            for (int i = 0; i < 4; i++) D2[m][j][i] = 0.f;

#pragma unroll
    for (int kt = 0; kt < 2; kt++)
#pragma unroll
        for (int j = 0; j < JC; j++)
#pragma unroll
            for (int m = 0; m < 2; m++) {
                mma_bf16(D2[m][j], kh[kt][m], B[kt][j].x, B[kt][j].y);
                mma_bf16(D2[m][j], kl[kt][m], B[kt][j].x, B[kt][j].y);
                mma_bf16(D2[m][j], kh[kt][m], B[kt][j].z, B[kt][j].w);
            }

#pragma unroll
    for (int j = 0; j < JC; j++) {
        int n0 = (nts + j) * 8 + 2 * t;
        float* o0 = outb + (size_t)n0 * HW + colA;
        if (n0 < N_PER) {
            o0[0]  = D2[0][j][0]; o0[8]  = D2[0][j][2];
            o0[16] = D2[1][j][0]; o0[24] = D2[1][j][2];
        }
        if (n0 + 1 < N_PER) {
            o0[HW]      = D2[0][j][1]; o0[HW + 8]  = D2[0][j][3];
            o0[HW + 16] = D2[1][j][1]; o0[HW + 24] = D2[1][j][3];
        }
    }
}

// ---------------------------------------------------------------------------
// Fused MMA kernel. Block = 128 px; 4 warps, warp = 32 px (2 m16 frags).
// smem = feat double-buffer only (33.8KB) -> 4 CTAs/SM. kw/qf frags from L2.
// ---------------------------------------------------------------------------
__global__ void __launch_bounds__(128, 4)
seg_mma(const float* __restrict__ feat_map,
        const float* __restrict__ key_b,
        float* __restrict__ out) {
    extern __shared__ char sm[];
    float* feat_s = (float*)sm;
    float* key_s  = (float*)(sm + SM_KEY);              // [32 o][FSTR px]

    const int tid  = threadIdx.x;
    const int w    = tid >> 5, lane = tid & 31;
    const int t    = lane & 3, g = lane >> 2;
    const int b    = blockIdx.y;
    const int p0   = blockIdx.x * 128;
    const int colA = 32 * w + g;

    const u32 sb = (u32)__cvta_generic_to_shared(sm);
    const float* fm = feat_map + (size_t)b * IN_DIM * HW + p0;

    // feat chunk 0
#pragma unroll
    for (int i = 0; i < 8; i++) {
        int f = i * 128 + tid;
        int row = f >> 5, c4 = f & 31;
        cp16(sb + SM_FEAT0 + (u32)(row * (FSTR * 4) + c4 * 16),
             fm + (size_t)row * HW + c4 * 4);
    }
    CP_COMMIT();

    // ---- Stage 1: K loop, 8 chunks x 32 c, double buffered ----
    float D1[2][4][4];
#pragma unroll
    for (int m = 0; m < 2; m++)
#pragma unroll
        for (int nt = 0; nt < 4; nt++)
#pragma unroll
            for (int i = 0; i < 4; i++) D1[m][nt][i] = 0.f;

    for (int chunk = 0; chunk < 8; chunk++) {
        CP_WAITALL();
        __syncthreads();
        const int buf = chunk & 1;

        if (chunk + 1 < 8) {
            const float* src = fm + (size_t)(chunk + 1) * 32 * HW;
            const u32 dstb = sb + (buf ^ 1) * SM_FEAT1;
#pragma unroll
            for (int i = 0; i < 8; i++) {
                int f = i * 128 + tid;
                int row = f >> 5, c4 = f & 31;
                cp16(dstb + (u32)(row * (FSTR * 4) + c4 * 16),
                     src + (size_t)row * HW + c4 * 4);
            }
            CP_COMMIT();
        }

        const float* fb = feat_s + buf * (SM_FEAT1 / 4);
#pragma unroll
        for (int ksl = 0; ksl < 2; ksl++) {
            const int kt = chunk * 2 + ksl;
            const int rb = ksl * 16 + 2 * t;
            uint4 B0 = __ldg(&g_kwf[(kt * 4 + 0) * 32 + lane]);
            uint4 B1 = __ldg(&g_kwf[(kt * 4 + 1) * 32 + lane]);
            uint4 B2 = __ldg(&g_kwf[(kt * 4 + 2) * 32 + lane]);
            uint4 B3 = __ldg(&g_kwf[(kt * 4 + 3) * 32 + lane]);

            u32 ah[2][4], al[2][4];
#pragma unroll
            for (int m = 0; m < 2; m++) {
                int c0 = colA + m * 16;
                float f00 = fb[(rb)     * FSTR + c0];
                float f01 = fb[(rb + 1) * FSTR + c0];
                float f10 = fb[(rb)     * FSTR + c0 + 8];
                float f11 = fb[(rb + 1) * FSTR + c0 + 8];
                float f20 = fb[(rb + 8) * FSTR + c0];
                float f21 = fb[(rb + 9) * FSTR + c0];
                float f30 = fb[(rb + 8) * FSTR + c0 + 8];
                float f31 = fb[(rb + 9) * FSTR + c0 + 8];
                ah[m][0] = split_pair(f00, f01, al[m][0]);
                ah[m][1] = split_pair(f10, f11, al[m][1]);
                ah[m][2] = split_pair(f20, f21, al[m][2]);
                ah[m][3] = split_pair(f30, f31, al[m][3]);
            }
#pragma unroll
            for (int m = 0; m < 2; m++) {
                mma_bf16(D1[m][0], ah[m], B0.x, B0.y);
                mma_bf16(D1[m][0], al[m], B0.x, B0.y);
                mma_bf16(D1[m][0], ah[m], B0.z, B0.w);
                mma_bf16(D1[m][1], ah[m], B1.x, B1.y);
                mma_bf16(D1[m][1], al[m], B1.x, B1.y);
                mma_bf16(D1[m][1], ah[m], B1.z, B1.w);
                mma_bf16(D1[m][2], ah[m], B2.x, B2.y);
                mma_bf16(D1[m][2], al[m], B2.x, B2.y);
                mma_bf16(D1[m][2], ah[m], B2.z, B2.w);
                mma_bf16(D1[m][3], ah[m], B3.x, B3.y);
                mma_bf16(D1[m][3], al[m], B3.x, B3.y);
                mma_bf16(D1[m][3], ah[m], B3.z, B3.w);
            }
        }
    }

    __syncthreads();      // all feat reads done before key_s overwrites buf0
#pragma unroll
    for (int m = 0; m < 2; m++)
#pragma unroll
        for (int nt = 0; nt < 4; nt++)
#pragma unroll
            for (int i = 0; i < 4; i++) {
                int o  = nt * 8 + 2 * t + (i & 1);
                int px = colA + m * 16 + ((i & 2) ? 8 : 0);
                key_s[o * FSTR + px] = D1[m][nt][i] + key_b[o];
            }
    __syncthreads();                            // key_s complete

    // ---- Stage 2: hoist key fragments once ----
    u32 kh[2][2][4], kl[2][2][4];
#pragma unroll
    for (int kt = 0; kt < 2; kt++) {
        const int rb = kt * 16 + 2 * t;
#pragma unroll
        for (int m = 0; m < 2; m++) {
            int c0 = colA + m * 16;
            float k00 = key_s[(rb)     * FSTR + c0];
            float k01 = key_s[(rb + 1) * FSTR + c0];
            float k10 = key_s[(rb)     * FSTR + c0 + 8];
            float k11 = key_s[(rb + 1) * FSTR + c0 + 8];
            float k20 = key_s[(rb + 8) * FSTR + c0];
            float k21 = key_s[(rb + 9) * FSTR + c0];
            float k30 = key_s[(rb + 8) * FSTR + c0 + 8];
            float k31 = key_s[(rb + 9) * FSTR + c0 + 8];
            kh[kt][m][0] = split_pair(k00, k01, kl[kt][m][0]);
            kh[kt][m][1] = split_pair(k10, k11, kl[kt][m][1]);
            kh[kt][m][2] = split_pair(k20, k21, kl[kt][m][2]);
            kh[kt][m][3] = split_pair(k30, k31, kl[kt][m][3]);
        }
    }

    // wait for qproj's g_qf (PDL)
    cudaGridDependencySynchronize();

    const uint4* qf_b = g_qf + (size_t)b * 2 * NT2P * 32;
    float* outb = out + (size_t)b * N_PER * HW + p0;
#pragma unroll 1
    for (int c9 = 0; c9 < 9; c9++)
        stage2_chunk<4>(c9 * 4, qf_b, outb, kh, kl, lane, t, colA);
    stage2_chunk<2>(36, qf_b, outb, kh, kl, lane, t, colA);
}

// ---------------------------------------------------------------------------
extern "C" void kernel_launch(void* const* d_in, const int* in_sizes, int n_in,
                              void* d_out, int out_size) {
    const float* in_feats = (const float*)d_in[0];   // [1200,256]
    const float* feat_map = (const float*)d_in[1];   // [4,256,160,160]
    const float* qry_w    = (const float*)d_in[2];   // [32,256]
    const float* qry_b    = (const float*)d_in[3];   // [32]
    const float* key_w    = (const float*)d_in[4];   // [32,256]
    const float* key_b    = (const float*)d_in[5];   // [32]
    float* out = (float*)d_out;                      // [1200,160,160]

    cudaFuncSetAttribute(qproj_kernel, cudaFuncAttributeMaxDynamicSharedMemorySize, QP_TOTAL);
    cudaFuncSetAttribute(seg_mma, cudaFuncAttributeMaxDynamicSharedMemorySize, SM_TOTAL);

    // qproj: packs kw frags (first 8 blocks), triggers PDL after, computes q
    dim3 qgrid(38, BATCH);
    qproj_kernel<<<qgrid, 256, QP_TOTAL>>>(in_feats, qry_w, qry_b, key_w);

    // seg: PDL-launch; stage-1 overlaps qproj; GDS guards qf reads
    cudaLaunchConfig_t cfg = {};
    cfg.gridDim  = dim3(HW / 128, BATCH);            // (200, 4)
    cfg.blockDim = dim3(128, 1, 1);
    cfg.dynamicSmemBytes = SM_TOTAL;
    cfg.stream = 0;
    cudaLaunchAttribute attrs[1];
    attrs[0].id = cudaLaunchAttributeProgrammaticStreamSerialization;
    attrs[0].val.programmaticStreamSerializationAllowed = 1;
    cfg.attrs = attrs;
    cfg.numAttrs = 1;
    cudaLaunchKernelEx(&cfg, seg_mma, feat_map, key_b, out);
}

// round 11
// speedup vs baseline: 1.0708x; 1.0708x over previous
#include <cuda_runtime.h>
#include <cstdint>

// Fixed problem shapes
#define BATCH   4
#define N_PER   300
#define IN_DIM  256
#define KEY_DIM 32
#define HW      25600       // 160*160
#define NT2P    40          // stage2 n-tiles padded (300->320)
#define FSTR    132         // feat/key smem row stride (floats)

// seg_mma smem byte offsets (dynamic)
#define SM_FEAT0 0
#define SM_FEAT1 16896      // 32*132*4
#define SM_KEY   0          // key tile [32 o][FSTR] overlaps feat buf0
#define SM_QF    33792
#define SM_TOTAL 74752      // 33792 + 40*2*32*16

// qproj smem: w [32][65 float4] + x [8][64 float4] + q [8][32] f32
#define QP_W     0
#define QP_X     33280
#define QP_Q     41472
#define QP_TOTAL 42496

typedef unsigned int u32;

__device__ uint4 g_kwf[16 * 4 * 32];            // [kt16][nt][lane] hi/lo frag
__device__ uint4 g_qf[BATCH * 2 * NT2P * 32];   // [b][kt16][nt][lane] (.bss zero)

// ---------------------------------------------------------------------------
__device__ __forceinline__ u32 packbf(float flo, float fhi) {
    u32 r; asm("cvt.rn.bf16x2.f32 %0, %1, %2;" : "=r"(r) : "f"(fhi), "f"(flo));
    return r;
}
__device__ __forceinline__ u32 split_pair(float f0, float f1, u32& lo) {
    u32 h = packbf(f0, f1);
    float h0 = __uint_as_float(h << 16);
    float h1 = __uint_as_float(h & 0xffff0000u);
    lo = packbf(f0 - h0, f1 - h1);
    return h;
}
__device__ __forceinline__ void mma_bf16(float d[4], const u32 a[4], u32 b0, u32 b1) {
    asm volatile(
        "mma.sync.aligned.m16n8k16.row.col.f32.bf16.bf16.f32 "
        "{%0,%1,%2,%3}, {%4,%5,%6,%7}, {%8,%9}, {%0,%1,%2,%3};"
        : "+f"(d[0]), "+f"(d[1]), "+f"(d[2]), "+f"(d[3])
        : "r"(a[0]), "r"(a[1]), "r"(a[2]), "r"(a[3]), "r"(b0), "r"(b1));
}
__device__ __forceinline__ void cp16(u32 saddr, const void* g) {
    asm volatile("cp.async.cg.shared.global [%0], [%1], 16;" :: "r"(saddr), "l"(g));
}
#define CP_COMMIT()  asm volatile("cp.async.commit_group;" ::: "memory")
#define CP_WAITALL() asm volatile("cp.async.wait_group 0;" ::: "memory")

// ---------------------------------------------------------------------------
// qproj + q fragment pack + kw fragment pack (first 8 blocks of b=0).
// PDL trigger AFTER kw pack + fence: seg's stage-1 g_kwf reads are ordered.
// grid (38, 4), 256 thr, block = 8 q-rows.
// ---------------------------------------------------------------------------
__global__ void qproj_kernel(const float* __restrict__ in_feats,
                             const float* __restrict__ qry_w,
                             const float* __restrict__ qry_b,
                             const float* __restrict__ key_w) {
    extern __shared__ char qsm[];
    const float4* w_s4 = (const float4*)(qsm + QP_W);   // stride 65 float4/row
    const float4* x_s4 = (const float4*)(qsm + QP_X);   // stride 64 float4/row
    float*        q_s  = (float*)(qsm + QP_Q);          // [8][32]
    const u32 sb = (u32)__cvta_generic_to_shared(qsm);

    const int tid = threadIdx.x;
    const int b   = blockIdx.y;
    const int nt  = blockIdx.x;                 // n-tile (8 rows)
    const int n0  = nt * 8;

    // stage qry_w (32 x 64 float4, padded rows) + x rows
#pragma unroll
    for (int k = 0; k < 8; k++) {
        int idx = k * 256 + tid;
        int o = idx >> 6, i = idx & 63;
        cp16(sb + QP_W + (u32)(o * 65 + i) * 16, qry_w + o * IN_DIM + i * 4);
    }
#pragma unroll
    for (int k = 0; k < 2; k++) {
        int idx = k * 256 + tid;
        int row = idx >> 6, i = idx & 63;
        int n = n0 + row; if (n >= N_PER) n = N_PER - 1;
        cp16(sb + QP_X + (u32)idx * 16,
             in_feats + ((size_t)b * N_PER + n) * IN_DIM + i * 4);
    }
    CP_COMMIT();

    // kw fragment pack, then fence, then trigger (all blocks trigger)
    if (b == 0 && nt < 8) {
        int idx = nt * 256 + tid;               // 0..2047
        int lane = idx & 31, nt1 = (idx >> 5) & 3, kt = idx >> 7;
        int t = lane & 3, g = lane >> 2;
        int o  = nt1 * 8 + g;
        int k0 = kt * 16 + 2 * t;
        float w00 = key_w[o * IN_DIM + k0],     w01 = key_w[o * IN_DIM + k0 + 1];
        float w10 = key_w[o * IN_DIM + k0 + 8], w11 = key_w[o * IN_DIM + k0 + 9];
        uint4 v;
        v.x = split_pair(w00, w01, v.z);
        v.y = split_pair(w10, w11, v.w);
        g_kwf[idx] = v;
        __threadfence();
    }
    cudaTriggerProgrammaticLaunchCompletion();

    CP_WAITALL();
    __syncthreads();

    const int w    = tid >> 5, lane = tid & 31;
    const int n    = n0 + w;

    float a0 = 0.f, a1 = 0.f, a2 = 0.f, a3 = 0.f;
#pragma unroll 8
    for (int i = 0; i < 64; i++) {
        float4 wv = w_s4[lane * 65 + i];        // conflict-free LDS.128
        float4 xv = x_s4[w * 64 + i];           // broadcast
        a0 = fmaf(xv.x, wv.x, a0);
        a1 = fmaf(xv.y, wv.y, a1);
        a2 = fmaf(xv.z, wv.z, a2);
        a3 = fmaf(xv.w, wv.w, a3);
    }
    float q = (n < N_PER) ? (a0 + a1) + (a2 + a3) + qry_b[lane] : 0.f;
    q_s[w * 32 + lane] = q;
    __syncthreads();

    if (tid < 64) {
        int kt = tid >> 5;
        int t = lane & 3, g = lane >> 2;
        const float* qr = q_s + g * 32 + kt * 16 + 2 * t;
        uint4 v;
        v.x = split_pair(qr[0], qr[1], v.z);
        v.y = split_pair(qr[8], qr[9], v.w);
        g_qf[((size_t)(b * 2 + kt) * NT2P + nt) * 32 + lane] = v;
    }
}

// ---------------------------------------------------------------------------
// Stage-2 chunk: JC n-tiles, key fragments hoisted (kh/kl), qf from smem.
// ---------------------------------------------------------------------------
template<int JC>
__device__ __forceinline__ void stage2_chunk(
    int nts, const uint4* qf_s, float* outb,
    const u32 kh[2][2][4], const u32 kl[2][2][4],
    int lane, int t, int colA)
{
    float D2[2][JC][4];
#pragma unroll
    for (int m = 0; m < 2; m++)
#pragma unroll
        for (int j = 0; j < JC; j++)
#pragma unroll
            for (int i = 0; i < 4; i++) D2[m][j][i] = 0.f;

#pragma unroll
    for (int kt = 0; kt < 2; kt++) {
#pragma unroll
        for (int j = 0; j < JC; j++) {
            uint4 B = qf_s[(kt * NT2P + nts + j) * 32 + lane];
#pragma unroll
            for (int m = 0; m < 2; m++) {
                mma_bf16(D2[m][j], kh[kt][m], B.x, B.y);
                mma_bf16(D2[m][j], kl[kt][m], B.x, B.y);
                mma_bf16(D2[m][j], kh[kt][m], B.z, B.w);
            }
        }
    }

#pragma unroll
    for (int j = 0; j < JC; j++) {
        int n0 = (nts + j) * 8 + 2 * t;
        float* o0 = outb + (size_t)n0 * HW + colA;
        if (n0 < N_PER) {
            o0[0]  = D2[0][j][0]; o0[8]  = D2[0][j][2];
            o0[16] = D2[1][j][0]; o0[24] = D2[1][j][2];
        }
        if (n0 + 1 < N_PER) {
            o0[HW]      = D2[0][j][1]; o0[HW + 8]  = D2[0][j][3];
            o0[HW + 16] = D2[1][j][1]; o0[HW + 24] = D2[1][j][3];
        }
    }
}

// ---------------------------------------------------------------------------
// Fused MMA kernel (R9 structure: qf staged to smem, 3 CTAs/SM).
// Block = 128 px; 4 warps, warp = 32 px (2 m16 frags).
// ---------------------------------------------------------------------------
__global__ void __launch_bounds__(128, 3)
seg_mma(const float* __restrict__ feat_map,
        const float* __restrict__ key_b,
        float* __restrict__ out) {
    extern __shared__ char sm[];
    float* feat_s = (float*)sm;
    float* key_s  = (float*)(sm + SM_KEY);              // [32 o][FSTR px]
    const uint4* qf_s = (const uint4*)(sm + SM_QF);

    const int tid  = threadIdx.x;
    const int w    = tid >> 5, lane = tid & 31;
    const int t    = lane & 3, g = lane >> 2;
    const int b    = blockIdx.y;
    const int p0   = blockIdx.x * 128;
    const int colA = 32 * w + g;

    const u32 sb = (u32)__cvta_generic_to_shared(sm);
    const float* fm = feat_map + (size_t)b * IN_DIM * HW + p0;

    // feat chunk 0
#pragma unroll
    for (int i = 0; i < 8; i++) {
        int f = i * 128 + tid;
        int row = f >> 5, c4 = f & 31;
        cp16(sb + SM_FEAT0 + (u32)(row * (FSTR * 4) + c4 * 16),
             fm + (size_t)row * HW + c4 * 4);
    }
    CP_COMMIT();

    // ---- Stage 1: K loop, 8 chunks x 32 c, double buffered ----
    float D1[2][4][4];
#pragma unroll
    for (int m = 0; m < 2; m++)
#pragma unroll
        for (int nt = 0; nt < 4; nt++)
#pragma unroll
            for (int i = 0; i < 4; i++) D1[m][nt][i] = 0.f;

    for (int chunk = 0; chunk < 8; chunk++) {
        CP_WAITALL();
        __syncthreads();
        const int buf = chunk & 1;

        if (chunk + 1 < 8) {
            const float* src = fm + (size_t)(chunk + 1) * 32 * HW;
            const u32 dstb = sb + (buf ^ 1) * SM_FEAT1;
#pragma unroll
            for (int i = 0; i < 8; i++) {
                int f = i * 128 + tid;
                int row = f >> 5, c4 = f & 31;
                cp16(dstb + (u32)(row * (FSTR * 4) + c4 * 16),
                     src + (size_t)row * HW + c4 * 4);
            }
            CP_COMMIT();
        }

        const float* fb = feat_s + buf * (SM_FEAT1 / 4);
#pragma unroll
        for (int ksl = 0; ksl < 2; ksl++) {
            const int kt = chunk * 2 + ksl;
            const int rb = ksl * 16 + 2 * t;
            uint4 B0 = __ldg(&g_kwf[(kt * 4 + 0) * 32 + lane]);
            uint4 B1 = __ldg(&g_kwf[(kt * 4 + 1) * 32 + lane]);
            uint4 B2 = __ldg(&g_kwf[(kt * 4 + 2) * 32 + lane]);
            uint4 B3 = __ldg(&g_kwf[(kt * 4 + 3) * 32 + lane]);

            u32 ah[2][4], al[2][4];
#pragma unroll
            for (int m = 0; m < 2; m++) {
                int c0 = colA + m * 16;
                float f00 = fb[(rb)     * FSTR + c0];
                float f01 = fb[(rb + 1) * FSTR + c0];
                float f10 = fb[(rb)     * FSTR + c0 + 8];
                float f11 = fb[(rb + 1) * FSTR + c0 + 8];
                float f20 = fb[(rb + 8) * FSTR + c0];
                float f21 = fb[(rb + 9) * FSTR + c0];
                float f30 = fb[(rb + 8) * FSTR + c0 + 8];
                float f31 = fb[(rb + 9) * FSTR + c0 + 8];
                ah[m][0] = split_pair(f00, f01, al[m][0]);
                ah[m][1] = split_pair(f10, f11, al[m][1]);
                ah[m][2] = split_pair(f20, f21, al[m][2]);
                ah[m][3] = split_pair(f30, f31, al[m][3]);
            }
#pragma unroll
            for (int m = 0; m < 2; m++) {
                mma_bf16(D1[m][0], ah[m], B0.x, B0.y);
                mma_bf16(D1[m][0], al[m], B0.x, B0.y);
                mma_bf16(D1[m][0], ah[m], B0.z, B0.w);
                mma_bf16(D1[m][1], ah[m], B1.x, B1.y);
                mma_bf16(D1[m][1], al[m], B1.x, B1.y);
                mma_bf16(D1[m][1], ah[m], B1.z, B1.w);
                mma_bf16(D1[m][2], ah[m], B2.x, B2.y);
                mma_bf16(D1[m][2], al[m], B2.x, B2.y);
                mma_bf16(D1[m][2], ah[m], B2.z, B2.w);
                mma_bf16(D1[m][3], ah[m], B3.x, B3.y);
                mma_bf16(D1[m][3], al[m], B3.x, B3.y);
                mma_bf16(D1[m][3], ah[m], B3.z, B3.w);
            }
        }
    }

    __syncthreads();      // all feat reads done before key_s overwrites buf0
#pragma unroll
    for (int m = 0; m < 2; m++)
#pragma unroll
        for (int nt = 0; nt < 4; nt++)
#pragma unroll
            for (int i = 0; i < 4; i++) {
                int o  = nt * 8 + 2 * t + (i & 1);
                int px = colA + m * 16 + ((i & 2) ? 8 : 0);
                key_s[o * FSTR + px] = D1[m][nt][i] + key_b[o];
            }
    __syncthreads();                            // key_s complete

    // ---- hoist key fragments BEFORE the PDL wait (overlap) ----
    u32 kh[2][2][4], kl[2][2][4];
#pragma unroll
    for (int kt = 0; kt < 2; kt++) {
        const int rb = kt * 16 + 2 * t;
#pragma unroll
        for (int m = 0; m < 2; m++) {
            int c0 = colA + m * 16;
            float k00 = key_s[(rb)     * FSTR + c0];
            float k01 = key_s[(rb + 1) * FSTR + c0];
            float k10 = key_s[(rb)     * FSTR + c0 + 8];
            float k11 = key_s[(rb + 1) * FSTR + c0 + 8];
            float k20 = key_s[(rb + 8) * FSTR + c0];
            float k21 = key_s[(rb + 9) * FSTR + c0];
            float k30 = key_s[(rb + 8) * FSTR + c0 + 8];
            float k31 = key_s[(rb + 9) * FSTR + c0 + 8];
            kh[kt][m][0] = split_pair(k00, k01, kl[kt][m][0]);
            kh[kt][m][1] = split_pair(k10, k11, kl[kt][m][1]);
            kh[kt][m][2] = split_pair(k20, k21, kl[kt][m][2]);
            kh[kt][m][3] = split_pair(k30, k31, kl[kt][m][3]);
        }
    }

    // ---- wait for qproj (PDL), then stage qf once into smem ----
    cudaGridDependencySynchronize();
    {
        const uint4* qsrc = g_qf + (size_t)b * 2 * NT2P * 32;
#pragma unroll
        for (int k = 0; k < 20; k++) {
            int i = k * 128 + tid;              // 0..2559
            cp16(sb + SM_QF + (u32)i * 16, qsrc + i);
        }
    }
    CP_COMMIT();
    CP_WAITALL();
    __syncthreads();                            // qf_s ready

    float* outb = out + (size_t)b * N_PER * HW + p0;
#pragma unroll 1
    for (int c5 = 0; c5 < 4; c5++)
        stage2_chunk<8>(c5 * 8, qf_s, outb, kh, kl, lane, t, colA);
    stage2_chunk<6>(32, qf_s, outb, kh, kl, lane, t, colA);
}

// ---------------------------------------------------------------------------
extern "C" void kernel_launch(void* const* d_in, const int* in_sizes, int n_in,
                              void* d_out, int out_size) {
    const float* in_feats = (const float*)d_in[0];   // [1200,256]
    const float* feat_map = (const float*)d_in[1];   // [4,256,160,160]
    const float* qry_w    = (const float*)d_in[2];   // [32,256]
    const float* qry_b    = (const float*)d_in[3];   // [32]
    const float* key_w    = (const float*)d_in[4];   // [32,256]
    const float* key_b    = (const float*)d_in[5];   // [32]
    float* out = (float*)d_out;                      // [1200,160,160]

    cudaFuncSetAttribute(qproj_kernel, cudaFuncAttributeMaxDynamicSharedMemorySize, QP_TOTAL);
    cudaFuncSetAttribute(seg_mma, cudaFuncAttributeMaxDynamicSharedMemorySize, SM_TOTAL);

    // qproj: packs kw frags (first 8 blocks), triggers PDL after, computes q
    dim3 qgrid(38, BATCH);
    qproj_kernel<<<qgrid, 256, QP_TOTAL>>>(in_feats, qry_w, qry_b, key_w);

    // seg: PDL-launch; stage-1 overlaps qproj; GDS guards qf reads
    cudaLaunchConfig_t cfg = {};
    cfg.gridDim  = dim3(HW / 128, BATCH);            // (200, 4)
    cfg.blockDim = dim3(128, 1, 1);
    cfg.dynamicSmemBytes = SM_TOTAL;
    cfg.stream = 0;
    cudaLaunchAttribute attrs[1];
    attrs[0].id = cudaLaunchAttributeProgrammaticStreamSerialization;
    attrs[0].val.programmaticStreamSerializationAllowed = 1;
    cfg.attrs = attrs;
    cfg.numAttrs = 1;
    cudaLaunchKernelEx(&cfg, seg_mma, feat_map, key_b, out);
}